// round 17
// baseline (speedup 1.0000x reference)
#include <cuda_runtime.h>

// ---------------------------------------------------------------------------
// Scratch (no allocation allowed -> __device__ globals)
// ---------------------------------------------------------------------------
static __device__ float g_s0[8*8*128*128];    // conv s0 out [8,8,128,128]
static __device__ float g_s1[8*16*64*64];     // [8,16,64,64]
static __device__ float g_s2[8*32*32*32];     // [8,32,32,32]
static __device__ float g_s3[8*64*16*16];     // [8,64,16,16]
static __device__ float g_l1[8*64*16*16];     // lw1 out
static __device__ float g_xl[8*64*16*16];     // lw2 out (local head)
static __device__ float g_c0[8*64*8*8];       // cw0 out
static __device__ float g_xg[8*64];           // fc3 out
static __device__ float g_bg[8*8*16*16];      // bilateral grid [B,8,16,16]
static __device__ float g_guide[8*1024*1024]; // guide map [B,1024,1024]

__device__ __forceinline__ float relu_(float x){ return fmaxf(x, 0.0f); }

__device__ __forceinline__ float warp_sum(float v){
    #pragma unroll
    for (int o = 16; o > 0; o >>= 1) v += __shfl_down_sync(0xffffffffu, v, o);
    return v;
}

// Gaussian(sigma=2), 17 taps, normalized. Compile-time literals -> FFMA-imm.
static __device__ constexpr float GW[17] = {
    6.691630e-05f, 4.363500e-04f, 2.215960e-03f, 8.764310e-03f,
    2.699596e-02f, 6.475993e-02f, 1.209875e-01f, 1.760357e-01f,
    1.994747e-01f,
    1.760357e-01f, 1.209875e-01f, 6.475993e-02f, 2.699596e-02f,
    8.764310e-03f, 2.215960e-03f, 4.363500e-04f, 6.691630e-05f
};

__device__ __forceinline__ int reflect1024(int i) {
    return i < 0 ? -i : (i > 1023 ? 2046 - i : i);
}

// ---------------------------------------------------------------------------
// convf3: 3x3 conv (pad=1, stride S). Whole input staged once per block with
// register-batched loads (8 LDG in flight -> 8 STS), 256 threads, one sync.
// ---------------------------------------------------------------------------
template<int CIN, int S, int COB, int CPT, int TY, int TX, int XG, bool RELU, bool HB>
__global__ void convf3_kernel(const float* __restrict__ in, const float* __restrict__ wt,
                              const float* __restrict__ bias, float* __restrict__ out,
                              int HIN, int WIN, int Cout, int HOUT, int WOUT, int tilesX)
{
    constexpr int TILEW = TX*XG;
    constexpr int PH  = (TY-1)*S + 3;
    constexpr int PW  = (TILEW-1)*S + 3;
    constexpr int PWP = (PW % 2 == 0) ? PW + 1 : PW;
    constexpr int CG  = COB/CPT;
    constexpr int NT  = CG*TY*XG;
    constexpr int WR  = (TX-1)*S + 3;
    constexpr int TOT = CIN*PH*PW;
    constexpr int WTOT = COB*CIN*9;
    constexpr int NB  = (TOT + NT*8 - 1)/(NT*8);

    extern __shared__ float sm[];
    float* sIn = sm;
    float* sW  = sm + CIN*PH*PWP;

    const int b     = blockIdx.z;
    const int co0   = blockIdx.y * COB;
    const int tileX = (blockIdx.x % tilesX) * TILEW;
    const int tileY = (blockIdx.x / tilesX) * TY;
    const int tid   = threadIdx.x;

    const int iy0 = tileY*S - 1, ix0 = tileX*S - 1;
    const float* inb = in + (long)b*CIN*HIN*WIN;

    #pragma unroll 1
    for (int bb = 0; bb < NB; bb++) {
        float v[8];
        #pragma unroll
        for (int j = 0; j < 8; j++) {
            int i = (bb*8 + j)*NT + tid;
            v[j] = 0.0f;
            if (i < TOT) {
                int ci = i / (PH*PW); int rem = i - ci*(PH*PW);
                int r = rem / PW;     int c = rem - r*PW;
                int iy = iy0 + r, ix = ix0 + c;
                if ((unsigned)iy < (unsigned)HIN && (unsigned)ix < (unsigned)WIN)
                    v[j] = __ldg(&inb[(ci*HIN + iy)*WIN + ix]);
            }
        }
        #pragma unroll
        for (int j = 0; j < 8; j++) {
            int i = (bb*8 + j)*NT + tid;
            if (i < TOT) {
                int ci = i / (PH*PW); int rem = i - ci*(PH*PW);
                int r = rem / PW;     int c = rem - r*PW;
                sIn[(ci*PH + r)*PWP + c] = v[j];
            }
        }
    }
    for (int i = tid; i < WTOT; i += NT)
        sW[i] = __ldg(&wt[(long)co0*CIN*9 + i]);
    __syncthreads();

    const int y  = tid % TY;
    const int cg = (tid / TY) % CG;
    const int xg = tid / (TY*CG);

    float acc[CPT][TX];
    #pragma unroll
    for (int c = 0; c < CPT; c++)
        #pragma unroll
        for (int x = 0; x < TX; x++) acc[c][x] = 0.0f;

    #pragma unroll 1
    for (int ci = 0; ci < CIN; ci++) {
        float w[CPT][9];
        #pragma unroll
        for (int c = 0; c < CPT; c++)
            #pragma unroll
            for (int k = 0; k < 9; k++)
                w[c][k] = sW[(cg*CPT + c)*CIN*9 + ci*9 + k];
        #pragma unroll
        for (int ky = 0; ky < 3; ky++) {
            const float* rp = &sIn[(ci*PH + y*S + ky)*PWP + xg*TX*S];
            float row[WR];
            #pragma unroll
            for (int j = 0; j < WR; j++) row[j] = rp[j];
            #pragma unroll
            for (int x = 0; x < TX; x++)
                #pragma unroll
                for (int kx = 0; kx < 3; kx++)
                    #pragma unroll
                    for (int c = 0; c < CPT; c++)
                        acc[c][x] = fmaf(row[x*S + kx], w[c][ky*3 + kx], acc[c][x]);
        }
    }

    #pragma unroll
    for (int c = 0; c < CPT; c++) {
        int co = co0 + cg*CPT + c;
        float bv = HB ? bias[co] : 0.0f;
        #pragma unroll
        for (int x = 0; x < TX; x++) {
            float v = acc[c][x] + bv;
            if (RELU) v = relu_(v);
            out[((b*Cout + co)*HOUT + tileY + y)*WOUT + tileX + xg*TX + x] = v;
        }
    }
}

// ---------------------------------------------------------------------------
// s0: in = concat(nearest(lqs,256), evs) [8,18,256,256] -> conv3x3 s2 p1 relu
// ---------------------------------------------------------------------------
__global__ void s0f_kernel(const float* __restrict__ lqs, const float* __restrict__ evs,
                           const float* __restrict__ wt,  const float* __restrict__ bias,
                           float* __restrict__ out)
{
    constexpr int PH = 33, PW = 33, PWP = 33, NT = 256;
    constexpr int TOT = 18*PH*PW;
    constexpr int NB  = (TOT + NT*16 - 1)/(NT*16);
    extern __shared__ float sm[];
    float* sIn = sm;
    float* sW  = sm + 18*PH*PWP;

    const int b     = blockIdx.z;
    const int tileX = (blockIdx.x % 8) * 16;
    const int tileY = (blockIdx.x / 8) * 16;
    const int tid   = threadIdx.x;

    const int iy0 = tileY*2 - 1, ix0 = tileX*2 - 1;

    #pragma unroll 1
    for (int bb = 0; bb < NB; bb++) {
        float v[16];
        #pragma unroll
        for (int j = 0; j < 16; j++) {
            int i = (bb*16 + j)*NT + tid;
            v[j] = 0.0f;
            if (i < TOT) {
                int ci = i / (PH*PW); int rem = i - ci*(PH*PW);
                int r = rem / PW;     int c = rem - r*PW;
                int iy = iy0 + r, ix = ix0 + c;
                if ((unsigned)iy < 256u && (unsigned)ix < 256u) {
                    if (ci < 3) v[j] = __ldg(&lqs[(b*3 + ci)*1048576 + iy*4096 + ix*4]);
                    else        v[j] = __ldg(&evs[(b*15 + (ci-3))*65536 + iy*256 + ix]);
                }
            }
        }
        #pragma unroll
        for (int j = 0; j < 16; j++) {
            int i = (bb*16 + j)*NT + tid;
            if (i < TOT) {
                int ci = i / (PH*PW); int rem = i - ci*(PH*PW);
                int r = rem / PW;     int c = rem - r*PW;
                sIn[(ci*PH + r)*PWP + c] = v[j];
            }
        }
    }
    for (int i = tid; i < 8*18*9; i += NT) sW[i] = __ldg(&wt[i]);
    __syncthreads();

    const int y  = tid % 16;
    const int cg = (tid / 16) % 8;
    const int xg = tid / 128;

    float acc[8];
    #pragma unroll
    for (int x = 0; x < 8; x++) acc[x] = 0.0f;

    #pragma unroll 1
    for (int ci = 0; ci < 18; ci++) {
        float w[9];
        #pragma unroll
        for (int k = 0; k < 9; k++) w[k] = sW[(cg*18 + ci)*9 + k];
        #pragma unroll
        for (int ky = 0; ky < 3; ky++) {
            const float* rp = &sIn[(ci*PH + y*2 + ky)*PWP + xg*16];
            float row[17];
            #pragma unroll
            for (int j = 0; j < 17; j++) row[j] = rp[j];
            #pragma unroll
            for (int x = 0; x < 8; x++)
                #pragma unroll
                for (int kx = 0; kx < 3; kx++)
                    acc[x] = fmaf(row[x*2 + kx], w[ky*3 + kx], acc[x]);
        }
    }

    float bv = bias[cg];
    #pragma unroll
    for (int x = 0; x < 8; x++)
        out[((b*8 + cg)*128 + tileY + y)*128 + tileX + xg*8 + x] = relu_(acc[x] + bv);
}

// ---------------------------------------------------------------------------
// Fused cw1 (conv3x3 s2: [64,8,8]->[64,4,4]) + FC 1024->256->128->64.
// ---------------------------------------------------------------------------
__global__ void cw1fc_kernel(const float* __restrict__ c0,
                             const float* __restrict__ cw1, const float* __restrict__ cb1,
                             const float* __restrict__ fw1, const float* __restrict__ fb1,
                             const float* __restrict__ fw2, const float* __restrict__ fb2,
                             const float* __restrict__ fw3, const float* __restrict__ fb3,
                             float* __restrict__ xg)
{
    extern __shared__ float sm[];
    float* sC  = sm;             // 7040
    float* sWt = sC + 7040;      // 36864
    float* sc1 = sWt + 36864;    // 1024
    float* s1f = sc1 + 1024;     // 256
    float* s2f = s1f + 256;      // 128

    const int b = blockIdx.x, tid = threadIdx.x;

    for (int i = tid; i < 64*10*10; i += 256) {
        int ci = i / 100; int rem = i - ci*100;
        int r = rem / 10, c = rem - (rem/10)*10;
        int iy = r - 1, ix = c - 1;
        float v = 0.0f;
        if ((unsigned)iy < 8u && (unsigned)ix < 8u)
            v = c0[((b*64 + ci)*8 + iy)*8 + ix];
        sC[(ci*10 + r)*11 + c] = v;
    }
    for (int i = tid; i < 36864; i += 256) sWt[i] = cw1[i];
    __syncthreads();

    {
        int co = tid >> 2, y = tid & 3;
        float acc[4] = {0.0f, 0.0f, 0.0f, 0.0f};
        #pragma unroll 1
        for (int ci = 0; ci < 64; ci++) {
            float w[9];
            #pragma unroll
            for (int k = 0; k < 9; k++) w[k] = sWt[(co*64 + ci)*9 + k];
            #pragma unroll
            for (int ky = 0; ky < 3; ky++) {
                const float* rp = &sC[(ci*10 + y*2 + ky)*11];
                float row[9];
                #pragma unroll
                for (int j = 0; j < 9; j++) row[j] = rp[j];
                #pragma unroll
                for (int x = 0; x < 4; x++)
                    #pragma unroll
                    for (int kx = 0; kx < 3; kx++)
                        acc[x] = fmaf(row[x*2 + kx], w[ky*3 + kx], acc[x]);
            }
        }
        float bv = cb1[co];
        #pragma unroll
        for (int x = 0; x < 4; x++)
            sc1[co*16 + y*4 + x] = relu_(acc[x] + bv);
    }
    __syncthreads();

    const int lane = tid & 31, wp = tid >> 5;

    for (int j0 = 0; j0 < 32; j0 += 4) {
        int o = wp*32 + j0;
        const float* w0 = fw1 + o*1024;
        float a0 = 0.0f, a1 = 0.0f, a2 = 0.0f, a3 = 0.0f;
        #pragma unroll 4
        for (int k = lane; k < 1024; k += 32) {
            float xv = sc1[k];
            a0 = fmaf(w0[k],        xv, a0);
            a1 = fmaf(w0[k + 1024], xv, a1);
            a2 = fmaf(w0[k + 2048], xv, a2);
            a3 = fmaf(w0[k + 3072], xv, a3);
        }
        a0 = warp_sum(a0); a1 = warp_sum(a1); a2 = warp_sum(a2); a3 = warp_sum(a3);
        if (lane == 0) {
            s1f[o]   = relu_(a0 + fb1[o]);
            s1f[o+1] = relu_(a1 + fb1[o+1]);
            s1f[o+2] = relu_(a2 + fb1[o+2]);
            s1f[o+3] = relu_(a3 + fb1[o+3]);
        }
    }
    __syncthreads();

    for (int j0 = 0; j0 < 16; j0 += 4) {
        int o = wp*16 + j0;
        const float* w0 = fw2 + o*256;
        float a0 = 0.0f, a1 = 0.0f, a2 = 0.0f, a3 = 0.0f;
        #pragma unroll
        for (int k = lane; k < 256; k += 32) {
            float xv = s1f[k];
            a0 = fmaf(w0[k],       xv, a0);
            a1 = fmaf(w0[k + 256], xv, a1);
            a2 = fmaf(w0[k + 512], xv, a2);
            a3 = fmaf(w0[k + 768], xv, a3);
        }
        a0 = warp_sum(a0); a1 = warp_sum(a1); a2 = warp_sum(a2); a3 = warp_sum(a3);
        if (lane == 0) {
            s2f[o]   = relu_(a0 + fb2[o]);
            s2f[o+1] = relu_(a1 + fb2[o+1]);
            s2f[o+2] = relu_(a2 + fb2[o+2]);
            s2f[o+3] = relu_(a3 + fb2[o+3]);
        }
    }
    __syncthreads();

    for (int j0 = 0; j0 < 8; j0 += 4) {
        int o = wp*8 + j0;
        const float* w0 = fw3 + o*128;
        float a0 = 0.0f, a1 = 0.0f, a2 = 0.0f, a3 = 0.0f;
        #pragma unroll
        for (int k = lane; k < 128; k += 32) {
            float xv = s2f[k];
            a0 = fmaf(w0[k],       xv, a0);
            a1 = fmaf(w0[k + 128], xv, a1);
            a2 = fmaf(w0[k + 256], xv, a2);
            a3 = fmaf(w0[k + 384], xv, a3);
        }
        a0 = warp_sum(a0); a1 = warp_sum(a1); a2 = warp_sum(a2); a3 = warp_sum(a3);
        if (lane == 0) {
            xg[b*64 + o]   = a0 + fb3[o];
            xg[b*64 + o+1] = a1 + fb3[o+1];
            xg[b*64 + o+2] = a2 + fb3[o+2];
            xg[b*64 + o+3] = a3 + fb3[o+3];
        }
    }
}

// ---------------------------------------------------------------------------
// bg = conv1x1(relu(xg[b,c] + xl[b,c,y,x]), fuw) + fub  -> [B,8,16,16]
// ---------------------------------------------------------------------------
__global__ void bg_kernel(const float* __restrict__ xl, const float* __restrict__ xg,
                          const float* __restrict__ fuw, const float* __restrict__ fub,
                          float* __restrict__ bg)
{
    int b = blockIdx.x, p = threadIdx.x;
    __shared__ float sxg[64];
    __shared__ float sw[8*64];
    if (p < 64) sxg[p] = xg[b*64 + p];
    for (int i = p; i < 512; i += 256) sw[i] = fuw[i];
    __syncthreads();
    float acc[8];
    #pragma unroll
    for (int g = 0; g < 8; g++) acc[g] = fub[g];
    for (int c = 0; c < 64; c++) {
        float f = relu_(sxg[c] + xl[(b*64 + c)*256 + p]);
        #pragma unroll
        for (int g = 0; g < 8; g++) acc[g] = fmaf(sw[g*64 + c], f, acc[g]);
    }
    #pragma unroll
    for (int g = 0; g < 8; g++) bg[(b*8 + g)*256 + p] = acc[g];
}

// ---------------------------------------------------------------------------
// guide2_kernel: FUSED h-blur + v-blur + 1x1 head + sigmoid -> guide map.
// Tile 32 wide x 64 tall; input staged 3x80x48 (reflect both dims).
// sIn padded to 49 cols (conflict-free h-blur reads); sMid stride 33
// (conflict-free writes + column reads). Taps are literals -> FFMA-imm.
// ---------------------------------------------------------------------------
__global__ __launch_bounds__(256, 2)
void guide2_kernel(const float* __restrict__ lqs,
                   const float* __restrict__ gw1, const float* __restrict__ gb1,
                   const float* __restrict__ gw2, const float* __restrict__ gb2,
                   float* __restrict__ guide)
{
    extern __shared__ float sm[];
    float* sIn  = sm;                    // 3*80*49 = 11760
    float* sMid = sm + 11760;            // 3*80*33 = 7920
    float* sW   = sMid + 7920;           // 81

    const int tid = threadIdx.x;
    const int x0 = blockIdx.x * 32;
    const int y0 = blockIdx.y * 64;
    const int b  = blockIdx.z;

    if (tid < 81)
        sW[tid] = (tid < 48) ? gw1[tid]
                : (tid < 64) ? gb1[tid - 48]
                : (tid < 80) ? gw2[tid - 64] : gb2[0];

    // Stage 3 x 80 x 48 with reflect (rows y0-8..y0+71, cols x0-8..x0+39).
    // 11520 elems, 45/thread, 8-deep batches.
    const float* base = lqs + (long)b*3*1048576;
    constexpr int TOTG = 3*80*48;
    #pragma unroll 1
    for (int bb = 0; bb < 6; bb++) {
        float v[8];
        int gy_[8], gc_[8], gch_[8];
        #pragma unroll
        for (int j = 0; j < 8; j++) {
            int i = (bb*8 + j)*256 + tid;
            v[j] = 0.0f;
            if (i < TOTG) {
                int ch = i / 3840; int rem = i - ch*3840;
                int r = rem / 48;  int c = rem - r*48;
                gch_[j] = ch; gy_[j] = r; gc_[j] = c;
                v[j] = __ldg(&base[(long)ch*1048576 +
                                   reflect1024(y0 - 8 + r)*1024 + reflect1024(x0 - 8 + c)]);
            }
        }
        #pragma unroll
        for (int j = 0; j < 8; j++) {
            int i = (bb*8 + j)*256 + tid;
            if (i < TOTG)
                sIn[(gch_[j]*80 + gy_[j])*49 + gc_[j]] = v[j];
        }
    }
    __syncthreads();

    // h-blur: 480 tasks (ch, row, half). Each produces 16 outputs from 32 in.
    #pragma unroll 1
    for (int s = tid; s < 480; s += 256) {
        int half = s & 1;
        int r    = (s >> 1) % 80;
        int ch   = s / 160;
        const float* rp = &sIn[(ch*80 + r)*49 + half*16];
        float w[32];
        #pragma unroll
        for (int j = 0; j < 32; j++) w[j] = rp[j];
        float* op = &sMid[(ch*80 + r)*33 + half*16];
        #pragma unroll
        for (int o = 0; o < 16; o++) {
            float a = 0.0f;
            #pragma unroll
            for (int k = 0; k < 17; k++) a = fmaf(GW[k], w[o + k], a);
            op[o] = a;
        }
    }
    __syncthreads();

    // v-blur + head: thread = (x = lane, rg = warp); 8 rows per thread.
    const int x  = tid & 31;
    const int rg = tid >> 5;          // 0..7
    const int gx = x0 + x;

    float c0[24], c1[24], c2[24];
    {
        const float* p0 = &sMid[(0*80 + rg*8)*33 + x];
        const float* p1 = &sMid[(1*80 + rg*8)*33 + x];
        const float* p2 = &sMid[(2*80 + rg*8)*33 + x];
        #pragma unroll
        for (int k = 0; k < 24; k++) {
            c0[k] = p0[k*33];
            c1[k] = p1[k*33];
            c2[k] = p2[k*33];
        }
    }
    #pragma unroll
    for (int d = 0; d < 8; d++) {
        float a0 = 0.0f, a1 = 0.0f, a2 = 0.0f;
        #pragma unroll
        for (int k = 0; k < 17; k++) {
            a0 = fmaf(GW[k], c0[d + k], a0);
            a1 = fmaf(GW[k], c1[d + k], a1);
            a2 = fmaf(GW[k], c2[d + k], a2);
        }
        float ssum = sW[80];
        #pragma unroll
        for (int o = 0; o < 16; o++) {
            float h = fmaf(sW[o*3], a0, fmaf(sW[o*3+1], a1, fmaf(sW[o*3+2], a2, sW[48+o])));
            h = relu_(h);
            ssum = fmaf(sW[64+o], h, ssum);
        }
        float sig = 1.0f / (1.0f + __expf(-ssum));
        int gy = y0 + rg*8 + d;
        guide[(long)b*1048576 + gy*1024 + gx] = 2.0f*sig - 0.5f;
    }
}

// ---------------------------------------------------------------------------
// slice_kernel: trilinear slice of bilateral grid using guide map. float4 I/O.
// ---------------------------------------------------------------------------
__global__ void slice_kernel(const float* __restrict__ guide,
                             const float* __restrict__ bg, float* __restrict__ out)
{
    int idx = blockIdx.x*256 + threadIdx.x;
    int b   = idx >> 18;
    int rem = idx & 0x3FFFF;
    int py  = rem >> 8;
    int px0 = (rem & 255) << 2;

    float4 g4 = ((const float4*)guide)[idx];
    float gv[4] = {g4.x, g4.y, g4.z, g4.w};

    float gyv = (py + 0.5f) * (1.0f/1024.0f) * 2.0f - 0.5f;
    float ys  = fminf(fmaxf(((gyv + 1.0f)*16.0f - 1.0f)*0.5f, 0.0f), 15.0f);
    float y0f = floorf(ys);
    int   y0  = (int)y0f;
    float fy  = ys - y0f;
    int   y1  = min(y0 + 1, 15);

    const float* bgb = bg + b*2048;
    float res[4];
    #pragma unroll
    for (int j = 0; j < 4; j++) {
        int px = px0 + j;
        float gxv = (px + 0.5f) * (1.0f/1024.0f) * 2.0f - 0.5f;
        float xs  = fminf(fmaxf(((gxv + 1.0f)*16.0f - 1.0f)*0.5f, 0.0f), 15.0f);
        float x0f = floorf(xs);
        int   x0  = (int)x0f;
        float fx  = xs - x0f;
        int   x1  = min(x0 + 1, 15);

        float zs  = fminf(fmaxf(((gv[j] + 1.0f)*8.0f - 1.0f)*0.5f, 0.0f), 7.0f);
        float z0f = floorf(zs);
        int   z0  = (int)z0f;
        float fz  = zs - z0f;
        int   z1  = min(z0 + 1, 7);

        float v000 = __ldg(&bgb[z0*256 + y0*16 + x0]);
        float v001 = __ldg(&bgb[z0*256 + y0*16 + x1]);
        float v010 = __ldg(&bgb[z0*256 + y1*16 + x0]);
        float v011 = __ldg(&bgb[z0*256 + y1*16 + x1]);
        float v100 = __ldg(&bgb[z1*256 + y0*16 + x0]);
        float v101 = __ldg(&bgb[z1*256 + y0*16 + x1]);
        float v110 = __ldg(&bgb[z1*256 + y1*16 + x0]);
        float v111 = __ldg(&bgb[z1*256 + y1*16 + x1]);

        float c00 = v000 + (v001 - v000)*fx;
        float c01 = v010 + (v011 - v010)*fx;
        float c10 = v100 + (v101 - v100)*fx;
        float c11 = v110 + (v111 - v110)*fx;
        float c0v = c00 + (c01 - c00)*fy;
        float c1v = c10 + (c11 - c10)*fy;
        res[j] = c0v + (c1v - c0v)*fz;
    }
    ((float4*)out)[idx] = make_float4(res[0], res[1], res[2], res[3]);
}

// ---------------------------------------------------------------------------
// kernel_launch
// ---------------------------------------------------------------------------
extern "C" void kernel_launch(void* const* d_in, const int* in_sizes, int n_in,
                              void* d_out, int out_size)
{
    const float* lqs = (const float*)d_in[0];
    const float* evs = (const float*)d_in[1];
    const float* gw1 = (const float*)d_in[2];
    const float* gb1 = (const float*)d_in[3];
    const float* gw2 = (const float*)d_in[4];
    const float* gb2 = (const float*)d_in[5];
    const float* sw0 = (const float*)d_in[6];
    const float* sb0 = (const float*)d_in[7];
    const float* sw1 = (const float*)d_in[8];
    const float* sb1 = (const float*)d_in[9];
    const float* sw2 = (const float*)d_in[10];
    const float* sb2 = (const float*)d_in[11];
    const float* sw3 = (const float*)d_in[12];
    const float* sb3 = (const float*)d_in[13];
    const float* cw0 = (const float*)d_in[14];
    const float* cb0 = (const float*)d_in[15];
    const float* cw1 = (const float*)d_in[16];
    const float* cb1 = (const float*)d_in[17];
    const float* fw1 = (const float*)d_in[18];
    const float* fb1 = (const float*)d_in[19];
    const float* fw2 = (const float*)d_in[20];
    const float* fb2 = (const float*)d_in[21];
    const float* fw3 = (const float*)d_in[22];
    const float* fb3 = (const float*)d_in[23];
    const float* lw1 = (const float*)d_in[24];
    const float* lb1 = (const float*)d_in[25];
    const float* lw2 = (const float*)d_in[26];
    const float* fuw = (const float*)d_in[27];
    const float* fub = (const float*)d_in[28];
    float* out = (float*)d_out;

    float *ps0, *ps1, *ps2, *ps3, *pl1, *pxl, *pc0, *pxg, *pbg, *pgd;
    cudaGetSymbolAddress((void**)&ps0, g_s0);
    cudaGetSymbolAddress((void**)&ps1, g_s1);
    cudaGetSymbolAddress((void**)&ps2, g_s2);
    cudaGetSymbolAddress((void**)&ps3, g_s3);
    cudaGetSymbolAddress((void**)&pl1, g_l1);
    cudaGetSymbolAddress((void**)&pxl, g_xl);
    cudaGetSymbolAddress((void**)&pc0, g_c0);
    cudaGetSymbolAddress((void**)&pxg, g_xg);
    cudaGetSymbolAddress((void**)&pbg, g_bg);
    cudaGetSymbolAddress((void**)&pgd, g_guide);

    // Dynamic smem sizes (bytes)
    const int SM_S0  = (18*33*33 + 8*18*9)  * 4;   //  83592
    const int SM_S1  = (8*33*33  + 8*8*9)   * 4;   //  37152
    const int SM_S2  = (16*33*33 + 8*16*9)  * 4;   //  74304
    const int SM_S3  = (32*17*33 + 8*32*9)  * 4;   //  81024
    const int SM_LW  = (64*10*19 + 8*64*9)  * 4;   //  67072
    const int SM_CW0 = (64*17*17 + 32*64*9) * 4;   // 147712
    const int SM_FC  = (7040 + 36864 + 1024 + 256 + 128) * 4;  // 181248
    const int SM_G2  = (11760 + 7920 + 81) * 4;    //  79044

    static cudaStream_t s_side = nullptr, s_cw = nullptr;
    static cudaEvent_t  ev_fork = nullptr, ev_gd = nullptr, ev_s3 = nullptr, ev_cw = nullptr;
    if (!s_side) {
        cudaStreamCreateWithFlags(&s_side, cudaStreamNonBlocking);
        cudaStreamCreateWithFlags(&s_cw,   cudaStreamNonBlocking);
        cudaEventCreateWithFlags(&ev_fork, cudaEventDisableTiming);
        cudaEventCreateWithFlags(&ev_gd,   cudaEventDisableTiming);
        cudaEventCreateWithFlags(&ev_s3,   cudaEventDisableTiming);
        cudaEventCreateWithFlags(&ev_cw,   cudaEventDisableTiming);
        cudaFuncSetAttribute(s0f_kernel, cudaFuncAttributeMaxDynamicSharedMemorySize, SM_S0);
        cudaFuncSetAttribute(convf3_kernel<16,2,8,1,16,8,2,true,true>,   cudaFuncAttributeMaxDynamicSharedMemorySize, SM_S2);
        cudaFuncSetAttribute(convf3_kernel<32,2,8,1,8,4,4,true,true>,    cudaFuncAttributeMaxDynamicSharedMemorySize, SM_S3);
        cudaFuncSetAttribute(convf3_kernel<64,1,8,1,8,4,4,true,true>,    cudaFuncAttributeMaxDynamicSharedMemorySize, SM_LW);
        cudaFuncSetAttribute(convf3_kernel<64,1,8,1,8,4,4,false,false>,  cudaFuncAttributeMaxDynamicSharedMemorySize, SM_LW);
        cudaFuncSetAttribute(convf3_kernel<64,2,32,1,8,8,1,true,true>,   cudaFuncAttributeMaxDynamicSharedMemorySize, SM_CW0);
        cudaFuncSetAttribute(cw1fc_kernel, cudaFuncAttributeMaxDynamicSharedMemorySize, SM_FC);
        cudaFuncSetAttribute(guide2_kernel, cudaFuncAttributeMaxDynamicSharedMemorySize, SM_G2);
    }

    // ---- fork: fused guide runs concurrent with the lowres trunk ----
    cudaEventRecord(ev_fork, 0);
    cudaStreamWaitEvent(s_side, ev_fork, 0);
    guide2_kernel<<<dim3(32, 16, 8), 256, SM_G2, s_side>>>(lqs, gw1, gb1, gw2, gb2, pgd);
    cudaEventRecord(ev_gd, s_side);

    // ---- lowres trunk (re-gridded convf3 chain) ----
    s0f_kernel<<<dim3(64, 1, 8), 256, SM_S0>>>(lqs, evs, sw0, sb0, ps0);
    convf3_kernel<8,2,8,1,16,8,2,true,true>
        <<<dim3(16, 2, 8), 256, SM_S1>>>(ps0, sw1, sb1, ps1, 128, 128, 16, 64, 64, 4);
    convf3_kernel<16,2,8,1,16,8,2,true,true>
        <<<dim3(4, 4, 8), 256, SM_S2>>>(ps1, sw2, sb2, ps2, 64, 64, 32, 32, 32, 2);
    convf3_kernel<32,2,8,1,8,4,4,true,true>
        <<<dim3(2, 8, 8), 256, SM_S3>>>(ps2, sw3, sb3, ps3, 32, 32, 64, 16, 16, 1);

    // ---- fork global head (cw0 -> cw1fc) onto s_cw, local head on main ----
    cudaEventRecord(ev_s3, 0);
    cudaStreamWaitEvent(s_cw, ev_s3, 0);
    convf3_kernel<64,2,32,1,8,8,1,true,true>
        <<<dim3(1, 2, 8), 256, SM_CW0, s_cw>>>(ps3, cw0, cb0, pc0, 16, 16, 64, 8, 8, 1);
    cw1fc_kernel<<<8, 256, SM_FC, s_cw>>>(pc0, cw1, cb1, fw1, fb1, fw2, fb2, fw3, fb3, pxg);
    cudaEventRecord(ev_cw, s_cw);

    convf3_kernel<64,1,8,1,8,4,4,true,true>
        <<<dim3(2, 8, 8), 256, SM_LW>>>(ps3, lw1, lb1, pl1, 16, 16, 64, 16, 16, 1);
    convf3_kernel<64,1,8,1,8,4,4,false,false>
        <<<dim3(2, 8, 8), 256, SM_LW>>>(pl1, lw2, (const float*)nullptr, pxl, 16, 16, 64, 16, 16, 1);

    // ---- join heads, build bilateral grid ----
    cudaStreamWaitEvent(0, ev_cw, 0);
    bg_kernel<<<8, 256>>>(pxl, pxg, fuw, fub, pbg);

    // ---- join guide; slice ----
    cudaStreamWaitEvent(0, ev_gd, 0);
    slice_kernel<<<8192, 256>>>(pgd, pbg, out);
}